// round 15
// baseline (speedup 1.0000x reference)
#include <cuda_runtime.h>
#include <math.h>

// Problem dims
#define BB 64     // batch
#define TT 110    // timesteps
#define PP 64     // series
#define HH 256    // hidden
#define KK 16     // connections
#define LL 100    // nets seq length

typedef unsigned long long u64;

// Output layout (tuple concat, all f32):
//   pred   (P,B,L,1) : 409600  @ 0
//   logvar (B,H)     : 16384   @ 409600
//   mu     (B,H)     : 16384   @ 425984
//   mean   (B,P)     : 4096    @ 442368
//   disp   (B,P)     : 4096    @ 446464

__device__ float g_z[BB * HH];                       // latent z scratch
__device__ float g_WThh[(size_t)PP * HH * 768];      // 48MB: Whh_nets transposed [p][k][768]
__device__ float g_WTih[(size_t)PP * KK * 768];      // 3MB:  Wih_nets transposed [p][k][768]
__device__ float g_WTenc[606208];                    // encoder weights transposed

#define OFF_HHL  0        // W_hh_left^T  [256][768]
#define OFF_IHL  196608   // W_ih_left^T  [64][768]
#define OFF_IH1  245760   // W_ih_1^T     [256][768]
#define OFF_MU   442368   // W_mu^T       [256][256]
#define OFF_STD  507904   // W_std^T      [256][256]
#define OFF_MEAN 573440   // W_mean^T     [256][64]
#define OFF_DISP 589824   // W_disp^T     [256][64]

__device__ __forceinline__ u64 pk2(float x) {
    u64 r; asm("mov.b64 %0, {%1, %1};" : "=l"(r) : "f"(x)); return r;
}
__device__ __forceinline__ u64 ffma2(u64 a, u64 b, u64 c) {
    u64 d; asm("fma.rn.f32x2 %0, %1, %2, %3;" : "=l"(d) : "l"(a), "l"(b), "l"(c)); return d;
}
__device__ __forceinline__ void upk2(u64 a, float& lo, float& hi) {
    asm("mov.b64 {%0, %1}, %2;" : "=f"(lo), "=f"(hi) : "l"(a));
}
__device__ __forceinline__ float fsig(float x) {
    return __fdividef(1.0f, 1.0f + __expf(-x));
}
__device__ __forceinline__ float ftanh_(float x) {
    float e = __expf(fminf(fmaxf(2.0f * x, -80.0f), 80.0f));
    return __fdividef(e - 1.0f, e + 1.0f);
}

// ------------------------------------------------------------------
// Launch 0: fused transpose of all 7 encoder matrices (blockIdx.z = m)
// ------------------------------------------------------------------
struct EncT7 {
    const float* in[7];
    float*       out[7];
    int          R[7];
    int          C[7];
};
__global__ void transpose_multi7(EncT7 e)
{
    __shared__ float tile[32][33];
    const int m = blockIdx.z;
    const float* __restrict__ in = e.in[m];
    float* __restrict__ out = e.out[m];
    const int R = e.R[m], C = e.C[m];
    const int x = blockIdx.x * 32 + threadIdx.x;
    const int ybase = blockIdx.y * 32;
    #pragma unroll
    for (int j = threadIdx.y; j < 32; j += 8) {
        int y = ybase + j;
        if (x < C && y < R) tile[j][threadIdx.x] = in[(size_t)y * C + x];
    }
    __syncthreads();
    const int xo = ybase + threadIdx.x;
    const int yobase = blockIdx.x * 32;
    #pragma unroll
    for (int j = threadIdx.y; j < 32; j += 8) {
        int yo = yobase + j;
        if (yo < C && xo < R) out[(size_t)yo * R + xo] = tile[threadIdx.x][j];
    }
}

// ------------------------------------------------------------------
// Launch 2: fused transpose of nets weights.
// ------------------------------------------------------------------
__global__ void transpose_nets(const float* __restrict__ Whh,
                               const float* __restrict__ Wih,
                               float* __restrict__ outhh,
                               float* __restrict__ outih)
{
    __shared__ float tile[32][33];
    const int z = blockIdx.z;
    const float* __restrict__ in;
    float* __restrict__ out;
    int C;
    if (z < PP) {
        in  = Whh   + (size_t)z * 768 * HH;
        out = outhh + (size_t)z * HH * 768;
        C = HH;
    } else {
        in  = Wih   + (size_t)(z - PP) * 768 * KK;
        out = outih + (size_t)(z - PP) * KK * 768;
        C = KK;
    }
    const int R = 768;
    const int x = blockIdx.x * 32 + threadIdx.x;
    const int ybase = blockIdx.y * 32;
    #pragma unroll
    for (int j = threadIdx.y; j < 32; j += 8) {
        int y = ybase + j;
        if (x < C && y < R) tile[j][threadIdx.x] = in[(size_t)y * C + x];
    }
    __syncthreads();
    const int xo = ybase + threadIdx.x;
    const int yobase = blockIdx.x * 32;
    #pragma unroll
    for (int j = threadIdx.y; j < 32; j += 8) {
        int yo = yobase + j;
        if (yo < C && xo < R) out[(size_t)yo * R + xo] = tile[threadIdx.x][j];
    }
}

// ------------------------------------------------------------------
// Launch 1: Encoder: gru_left (10 steps) -> gru_1 (1 step) -> heads + z
// ------------------------------------------------------------------
__global__ void __launch_bounds__(256) encoder_kernel(
    const float* __restrict__ X,
    const float* __restrict__ bih_l, const float* __restrict__ bhh_l,
    const float* __restrict__ bih1,  const float* __restrict__ bhh1,
    const float* __restrict__ bmu,   const float* __restrict__ bstd,
    const float* __restrict__ bmean, const float* __restrict__ bdisp,
    const float* __restrict__ z_noise,
    float* __restrict__ out_logvar, float* __restrict__ out_mu,
    float* __restrict__ out_mean,   float* __restrict__ out_disp)
{
    const int b = blockIdx.x;
    const int t = threadIdx.x;
    __shared__ float hs[HH];
    __shared__ float xs[PP];
    hs[t] = 0.0f;

    const float bir = bih_l[t]        + bhh_l[t];
    const float biz = bih_l[HH + t]   + bhh_l[HH + t];
    const float bin = bih_l[2*HH + t];
    const float bhn = bhh_l[2*HH + t];
    const float* __restrict__ Wh = g_WTenc + OFF_HHL;
    const float* __restrict__ Wi = g_WTenc + OFF_IHL;
    __syncthreads();

    for (int s = 0; s < 10; s++) {
        if (t < PP) xs[t] = X[((size_t)b * TT + s) * PP + t];
        __syncthreads();
        float ar = bir, az = biz, an = bin, gn = bhn;
        #pragma unroll 4
        for (int k = 0; k < HH; k++) {
            float hk = hs[k];
            ar += hk * Wh[k*768 + t];
            az += hk * Wh[k*768 + 256 + t];
            gn += hk * Wh[k*768 + 512 + t];
        }
        #pragma unroll 4
        for (int k = 0; k < PP; k++) {
            float xk = xs[k];
            ar += xk * Wi[k*768 + t];
            az += xk * Wi[k*768 + 256 + t];
            an += xk * Wi[k*768 + 512 + t];
        }
        float r  = fsig(ar);
        float zz = fsig(az);
        float n  = ftanh_(an + r * gn);
        float hnew = (1.0f - zz) * n + zz * hs[t];
        __syncthreads();
        hs[t] = hnew;
        __syncthreads();
    }

    {
        const float* __restrict__ W1 = g_WTenc + OFF_IH1;
        float ar = bih1[t]        + bhh1[t];
        float az = bih1[HH + t]   + bhh1[HH + t];
        float an = bih1[2*HH + t];
        float gn = bhh1[2*HH + t];
        #pragma unroll 4
        for (int k = 0; k < HH; k++) {
            float hk = hs[k];
            ar += hk * W1[k*768 + t];
            az += hk * W1[k*768 + 256 + t];
            an += hk * W1[k*768 + 512 + t];
        }
        float r  = fsig(ar);
        float zz = fsig(az);
        float n  = ftanh_(an + r * gn);
        float h1 = (1.0f - zz) * n;
        __syncthreads();
        hs[t] = h1;
        __syncthreads();
    }

    {
        float mu = bmu[t], lv = bstd[t];
        const float* __restrict__ Wm = g_WTenc + OFF_MU;
        const float* __restrict__ Ws = g_WTenc + OFF_STD;
        #pragma unroll 4
        for (int k = 0; k < HH; k++) {
            float hk = hs[k];
            mu += hk * Wm[k*256 + t];
            lv += hk * Ws[k*256 + t];
        }
        out_mu[b*HH + t]     = mu;
        out_logvar[b*HH + t] = lv;
        g_z[b*HH + t] = mu + expf(0.5f * lv) * z_noise[b*HH + t];

        if (t < PP) {
            float m = bmean[t], d = bdisp[t];
            const float* __restrict__ Wme = g_WTenc + OFF_MEAN;
            const float* __restrict__ Wd  = g_WTenc + OFF_DISP;
            #pragma unroll 4
            for (int k = 0; k < HH; k++) {
                float hk = hs[k];
                m += hk * Wme[k*64 + t];
                d += hk * Wd[k*64 + t];
            }
            m = expf(m);
            m = fminf(fmaxf(m, 1e-5f), 1e6f);
            d = log1pf(expf(d));
            d = fminf(fmaxf(d, 1e-4f), 1e4f);
            out_mean[b*PP + t] = m;
            out_disp[b*PP + t] = d;
        }
    }
}

// ------------------------------------------------------------------
// Launch 3: Per-series GRU nets — EXACT R13 hot loop (fixed SMEM bases,
// two barriers), with the serial inter-barrier section reduced to pure
// STS: next-x LDG issued at step top (1 reg crosses compute), and pred
// finalize moved to the next step's top via psum double-buffer.
// grid (64,4), 256 thr, 2 CTAs/SM, dynamic SMEM ~72KB/CTA.
// ------------------------------------------------------------------
#define BT 16
#define HST 20                 // hs row stride (16 batches + 4 pad)
#define WIH_F (KK * 768)       // 12288 floats = 48KB
#define PS_BUF 128             // 8 warps x 16 batches
#define NETS_SMEM_F (WIH_F + HH*HST + KK*HST + 2*PS_BUF + 16)

extern __shared__ float s_nets[];

__global__ void __launch_bounds__(256, 2) nets_kernel(
    const float* __restrict__ X,
    const int*   __restrict__ conn_idx,
    const float* __restrict__ bih,   // (P, 768)
    const float* __restrict__ bhh,   // (P, 768)
    const float* __restrict__ Wlin,  // (P, 1, 256)
    const float* __restrict__ blin,  // (P, 1)
    float* __restrict__ pred)        // (P, B, L, 1)
{
    const int p    = blockIdx.x;
    const int b0c  = blockIdx.y * BT;
    const int tid  = threadIdx.x;
    const int t    = tid;             // hidden unit
    const int lane = tid & 31;
    const int wg   = tid >> 5;        // warp 0..7

    float* wih_s = s_nets;                      // [16][768] staged input weights
    float* hs2   = s_nets + WIH_F;              // [k][16b] (stride 20) — single buffer
    float* xg2   = hs2 + HH*HST;                // [k][16b] — single buffer
    float* ps    = xg2 + KK*HST;                // [2][8][16] double-buffered psum
    int*   cidx  = (int*)(ps + 2*PS_BUF);       // [16]

    if (tid < KK) cidx[tid] = conn_idx[p*KK + tid];
    for (int i = tid; i < KK*HST; i += 256) xg2[i] = 0.0f;  // step 0 = zero row
    // stage input weights (step-invariant): 12288 floats, coalesced
    {
        const float* Wib = g_WTih + (size_t)p * WIH_F;
        for (int i = tid; i < WIH_F; i += 256) wih_s[i] = Wib[i];
    }
    #pragma unroll
    for (int j = 0; j < BT; j++)
        hs2[t*HST + j] = g_z[(size_t)(b0c + j) * HH + t];

    const size_t pb = (size_t)p * 768;
    const u64 brc2 = pk2(bih[pb + t]       + bhh[pb + t]);
    const u64 bzc2 = pk2(bih[pb + 256 + t] + bhh[pb + 256 + t]);
    const u64 bin2 = pk2(bih[pb + 512 + t]);
    const u64 bhn2 = pk2(bhh[pb + 512 + t]);
    const float wl  = Wlin[(size_t)p * HH + t];
    const float blv = blin[p];
    const float* __restrict__ Whp = g_WThh + (size_t)p * HH * 768 + t;  // [k][768]

    // per-thread gather role for next-x prefetch (16 b x 16 k)
    const int xb = tid >> 4, xk = tid & 15;

    __syncthreads();

    for (int l = 0; l < LL; l++) {
        // finalize pred for step l-1, overlapped with this step's compute
        // (ps[(l-1)&1] was completed last step; this step writes ps[l&1])
        if (l > 0 && tid < 16) {
            const float* pp_ = ps + ((l-1) & 1)*PS_BUF;
            float s = 0.0f;
            #pragma unroll
            for (int w = 0; w < 8; w++) s += pp_[w*16 + tid];
            pred[((size_t)(p*BB + b0c + tid)) * LL + (l-1)] = s + blv;
        }

        // prefetch next step's x (LDG hidden under the whole compute phase)
        float xnext = 0.0f;
        if (l < LL - 1)
            xnext = X[((size_t)(b0c + xb) * TT + (10 + l)) * PP + cidx[xk]];

        u64 ar2[8], az2[8], gi2[8], gh2[8];
        #pragma unroll
        for (int q = 0; q < 8; q++) { ar2[q]=brc2; az2[q]=bzc2; gi2[q]=bin2; gh2[q]=bhn2; }

        // input contribution (K = 16) — weights from SMEM (no LDG convoy)
        #pragma unroll
        for (int k = 0; k < KK; k++) {
            const float* r_ = wih_s + k * 768;
            const u64 wr = pk2(r_[t]);
            const u64 wz = pk2(r_[256 + t]);
            const u64 wn = pk2(r_[512 + t]);
            const ulonglong2* hp =
                reinterpret_cast<const ulonglong2*>(&xg2[k*HST]);
            #pragma unroll
            for (int q = 0; q < 4; q++) {
                ulonglong2 hv = hp[q];
                ar2[2*q]   = ffma2(hv.x, wr, ar2[2*q]);
                az2[2*q]   = ffma2(hv.x, wz, az2[2*q]);
                gi2[2*q]   = ffma2(hv.x, wn, gi2[2*q]);
                ar2[2*q+1] = ffma2(hv.y, wr, ar2[2*q+1]);
                az2[2*q+1] = ffma2(hv.y, wz, az2[2*q+1]);
                gi2[2*q+1] = ffma2(hv.y, wn, gi2[2*q+1]);
            }
        }

        // hidden contribution (H = 256) — chunks of 8 k:
        // phase 1 preloads 24 weight scalars; phase 2 is 192 FFMA2.
        #pragma unroll 1
        for (int kk = 0; kk < HH; kk += 8) {
            float wrf[8], wzf[8], wnf[8];
            #pragma unroll
            for (int j = 0; j < 8; j++) {
                const float* r_ = Whp + (size_t)(kk + j) * 768;
                wrf[j] = r_[0];
                wzf[j] = r_[256];
                wnf[j] = r_[512];
            }
            #pragma unroll
            for (int j = 0; j < 8; j++) {
                const u64 wr = pk2(wrf[j]);
                const u64 wz = pk2(wzf[j]);
                const u64 wn = pk2(wnf[j]);
                const ulonglong2* hp =
                    reinterpret_cast<const ulonglong2*>(&hs2[(kk + j)*HST]);
                #pragma unroll
                for (int q = 0; q < 4; q++) {
                    ulonglong2 hv = hp[q];
                    ar2[2*q]   = ffma2(hv.x, wr, ar2[2*q]);
                    az2[2*q]   = ffma2(hv.x, wz, az2[2*q]);
                    gh2[2*q]   = ffma2(hv.x, wn, gh2[2*q]);
                    ar2[2*q+1] = ffma2(hv.y, wr, ar2[2*q+1]);
                    az2[2*q+1] = ffma2(hv.y, wz, az2[2*q+1]);
                    gh2[2*q+1] = ffma2(hv.y, wn, gh2[2*q+1]);
                }
            }
        }

        // old h for the z-gate mix (read pre-barrier)
        float hold[16];
        #pragma unroll
        for (int j = 0; j < 4; j++) {
            float4 hv = *reinterpret_cast<const float4*>(&hs2[t*HST + 4*j]);
            hold[4*j]   = hv.x; hold[4*j+1] = hv.y;
            hold[4*j+2] = hv.z; hold[4*j+3] = hv.w;
        }

        float hnew[16];
        #pragma unroll
        for (int q = 0; q < 8; q++) {
            float a0,a1,z0,z1,i0,i1,n0,n1;
            upk2(ar2[q], a0, a1);
            upk2(az2[q], z0, z1);
            upk2(gi2[q], i0, i1);
            upk2(gh2[q], n0, n1);
            float r0 = fsig(a0), r1 = fsig(a1);
            float zz0 = fsig(z0), zz1 = fsig(z1);
            float nn0 = ftanh_(i0 + r0 * n0);
            float nn1 = ftanh_(i1 + r1 * n1);
            hnew[2*q]   = (1.0f - zz0) * nn0 + zz0 * hold[2*q];
            hnew[2*q+1] = (1.0f - zz1) * nn1 + zz1 * hold[2*q+1];
        }

        // pred partials into ps[l&1]: warp-reduce relu(h).wl per batch
        #pragma unroll
        for (int i = 0; i < 16; i++) {
            float v = fmaxf(hnew[i], 0.0f) * wl;
            v += __shfl_xor_sync(0xffffffffu, v, 16);
            v += __shfl_xor_sync(0xffffffffu, v, 8);
            v += __shfl_xor_sync(0xffffffffu, v, 4);
            v += __shfl_xor_sync(0xffffffffu, v, 2);
            v += __shfl_xor_sync(0xffffffffu, v, 1);
            if (lane == i) ps[(l & 1)*PS_BUF + wg*16 + i] = v;
        }

        __syncthreads();   // all reads of old hs2/xg2 + psum writes complete

        // inter-barrier section: pure STS only (BAR drains these natively)
        #pragma unroll
        for (int j = 0; j < 4; j++) {
            *reinterpret_cast<float4*>(&hs2[t*HST + 4*j]) =
                make_float4(hnew[4*j], hnew[4*j+1], hnew[4*j+2], hnew[4*j+3]);
        }
        if (l < LL - 1)
            xg2[xk*HST + xb] = xnext;

        __syncthreads();   // hs2/xg2 writes visible before next compute
    }

    // finalize pred for the last step ((LL-1)&1 = 1)
    if (tid < 16) {
        const float* pp_ = ps + 1*PS_BUF;
        float s = 0.0f;
        #pragma unroll
        for (int w = 0; w < 8; w++) s += pp_[w*16 + tid];
        pred[((size_t)(p*BB + b0c + tid)) * LL + (LL-1)] = s + blv;
    }
}

extern "C" void kernel_launch(void* const* d_in, const int* in_sizes, int n_in,
                              void* d_out, int out_size)
{
    const float* X         = (const float*)d_in[0];
    const int*   conn_idx  = (const int*)  d_in[1];
    const float* W_ih_left = (const float*)d_in[2];
    const float* W_hh_left = (const float*)d_in[3];
    const float* b_ih_left = (const float*)d_in[4];
    const float* b_hh_left = (const float*)d_in[5];
    const float* W_ih_1    = (const float*)d_in[6];
    // d_in[7] = W_hh_1: unused (hidden state is 0 for gru_1's single step)
    const float* b_ih_1    = (const float*)d_in[8];
    const float* b_hh_1    = (const float*)d_in[9];
    const float* W_mu      = (const float*)d_in[10];
    const float* b_mu      = (const float*)d_in[11];
    const float* W_std     = (const float*)d_in[12];
    const float* b_std     = (const float*)d_in[13];
    const float* W_mean    = (const float*)d_in[14];
    const float* b_mean    = (const float*)d_in[15];
    const float* W_disp    = (const float*)d_in[16];
    const float* b_disp    = (const float*)d_in[17];
    const float* W_ih_nets = (const float*)d_in[18];
    const float* W_hh_nets = (const float*)d_in[19];
    const float* b_ih_nets = (const float*)d_in[20];
    const float* b_hh_nets = (const float*)d_in[21];
    const float* W_lin     = (const float*)d_in[22];
    const float* b_lin     = (const float*)d_in[23];
    const float* z_noise   = (const float*)d_in[24];

    float* out = (float*)d_out;
    float* pred       = out;
    float* out_logvar = out + 409600;
    float* out_mu     = out + 409600 + 16384;
    float* out_mean   = out + 409600 + 2*16384;
    float* out_disp   = out + 409600 + 2*16384 + 4096;

    float *wthh, *wtih, *wtenc;
    cudaGetSymbolAddress((void**)&wthh,  g_WThh);
    cudaGetSymbolAddress((void**)&wtih,  g_WTih);
    cudaGetSymbolAddress((void**)&wtenc, g_WTenc);

    const int nets_smem = NETS_SMEM_F * 4;
    cudaFuncSetAttribute(nets_kernel,
                         cudaFuncAttributeMaxDynamicSharedMemorySize, nets_smem);

    dim3 tb(32, 8);

    // Launch 0: all 7 encoder-weight transposes fused
    EncT7 e;
    e.in[0] = W_hh_left; e.out[0] = wtenc + OFF_HHL;  e.R[0] = 768; e.C[0] = 256;
    e.in[1] = W_ih_left; e.out[1] = wtenc + OFF_IHL;  e.R[1] = 768; e.C[1] = 64;
    e.in[2] = W_ih_1;    e.out[2] = wtenc + OFF_IH1;  e.R[2] = 768; e.C[2] = 256;
    e.in[3] = W_mu;      e.out[3] = wtenc + OFF_MU;   e.R[3] = 256; e.C[3] = 256;
    e.in[4] = W_std;     e.out[4] = wtenc + OFF_STD;  e.R[4] = 256; e.C[4] = 256;
    e.in[5] = W_mean;    e.out[5] = wtenc + OFF_MEAN; e.R[5] = 64;  e.C[5] = 256;
    e.in[6] = W_disp;    e.out[6] = wtenc + OFF_DISP; e.R[6] = 64;  e.C[6] = 256;
    transpose_multi7<<<dim3(8, 24, 7), tb>>>(e);

    // Launch 1: encoder (needs launch 0)
    encoder_kernel<<<BB, 256>>>(
        X, b_ih_left, b_hh_left, b_ih_1, b_hh_1,
        b_mu, b_std, b_mean, b_disp, z_noise,
        out_logvar, out_mu, out_mean, out_disp);

    // Launch 2: nets weight transposes fused (hh: z<64, ih: z>=64)
    transpose_nets<<<dim3(8, 24, 2*PP), tb>>>(W_hh_nets, W_ih_nets, wthh, wtih);

    // Launch 3: nets (profiled slot)
    nets_kernel<<<dim3(PP, BB/BT), 256, nets_smem>>>(
        X, conn_idx, b_ih_nets, b_hh_nets, W_lin, b_lin, pred);
}

// round 16
// speedup vs baseline: 1.0773x; 1.0773x over previous
#include <cuda_runtime.h>
#include <math.h>

// Problem dims
#define BB 64     // batch
#define TT 110    // timesteps
#define PP 64     // series
#define HH 256    // hidden
#define KK 16     // connections
#define LL 100    // nets seq length

typedef unsigned long long u64;

// Output layout (tuple concat, all f32):
//   pred   (P,B,L,1) : 409600  @ 0
//   logvar (B,H)     : 16384   @ 409600
//   mu     (B,H)     : 16384   @ 425984
//   mean   (B,P)     : 4096    @ 442368
//   disp   (B,P)     : 4096    @ 446464

__device__ float g_z[BB * HH];                       // latent z scratch
__device__ float g_WThh[(size_t)PP * HH * 768];      // 48MB: Whh_nets transposed [p][k][768]
__device__ float g_WTih[(size_t)PP * KK * 768];      // 3MB:  Wih_nets transposed [p][k][768]
__device__ float g_WTenc[606208];                    // encoder weights transposed

#define OFF_HHL  0        // W_hh_left^T  [256][768]
#define OFF_IHL  196608   // W_ih_left^T  [64][768]
#define OFF_IH1  245760   // W_ih_1^T     [256][768]
#define OFF_MU   442368   // W_mu^T       [256][256]
#define OFF_STD  507904   // W_std^T      [256][256]
#define OFF_MEAN 573440   // W_mean^T     [256][64]
#define OFF_DISP 589824   // W_disp^T     [256][64]

__device__ __forceinline__ u64 pk2(float x) {
    u64 r; asm("mov.b64 %0, {%1, %1};" : "=l"(r) : "f"(x)); return r;
}
__device__ __forceinline__ u64 ffma2(u64 a, u64 b, u64 c) {
    u64 d; asm("fma.rn.f32x2 %0, %1, %2, %3;" : "=l"(d) : "l"(a), "l"(b), "l"(c)); return d;
}
__device__ __forceinline__ void upk2(u64 a, float& lo, float& hi) {
    asm("mov.b64 {%0, %1}, %2;" : "=f"(lo), "=f"(hi) : "l"(a));
}
__device__ __forceinline__ float fsig(float x) {
    return __fdividef(1.0f, 1.0f + __expf(-x));
}
__device__ __forceinline__ float ftanh_(float x) {
    float e = __expf(fminf(fmaxf(2.0f * x, -80.0f), 80.0f));
    return __fdividef(e - 1.0f, e + 1.0f);
}

// ------------------------------------------------------------------
// Launch 0: fused transpose of all 7 encoder matrices (blockIdx.z = m)
// ------------------------------------------------------------------
struct EncT7 {
    const float* in[7];
    float*       out[7];
    int          R[7];
    int          C[7];
};
__global__ void transpose_multi7(EncT7 e)
{
    __shared__ float tile[32][33];
    const int m = blockIdx.z;
    const float* __restrict__ in = e.in[m];
    float* __restrict__ out = e.out[m];
    const int R = e.R[m], C = e.C[m];
    const int x = blockIdx.x * 32 + threadIdx.x;
    const int ybase = blockIdx.y * 32;
    #pragma unroll
    for (int j = threadIdx.y; j < 32; j += 8) {
        int y = ybase + j;
        if (x < C && y < R) tile[j][threadIdx.x] = in[(size_t)y * C + x];
    }
    __syncthreads();
    const int xo = ybase + threadIdx.x;
    const int yobase = blockIdx.x * 32;
    #pragma unroll
    for (int j = threadIdx.y; j < 32; j += 8) {
        int yo = yobase + j;
        if (yo < C && xo < R) out[(size_t)yo * R + xo] = tile[threadIdx.x][j];
    }
}

// ------------------------------------------------------------------
// Launch 2: fused transpose of nets weights.
// ------------------------------------------------------------------
__global__ void transpose_nets(const float* __restrict__ Whh,
                               const float* __restrict__ Wih,
                               float* __restrict__ outhh,
                               float* __restrict__ outih)
{
    __shared__ float tile[32][33];
    const int z = blockIdx.z;
    const float* __restrict__ in;
    float* __restrict__ out;
    int C;
    if (z < PP) {
        in  = Whh   + (size_t)z * 768 * HH;
        out = outhh + (size_t)z * HH * 768;
        C = HH;
    } else {
        in  = Wih   + (size_t)(z - PP) * 768 * KK;
        out = outih + (size_t)(z - PP) * KK * 768;
        C = KK;
    }
    const int R = 768;
    const int x = blockIdx.x * 32 + threadIdx.x;
    const int ybase = blockIdx.y * 32;
    #pragma unroll
    for (int j = threadIdx.y; j < 32; j += 8) {
        int y = ybase + j;
        if (x < C && y < R) tile[j][threadIdx.x] = in[(size_t)y * C + x];
    }
    __syncthreads();
    const int xo = ybase + threadIdx.x;
    const int yobase = blockIdx.x * 32;
    #pragma unroll
    for (int j = threadIdx.y; j < 32; j += 8) {
        int yo = yobase + j;
        if (yo < C && xo < R) out[(size_t)yo * R + xo] = tile[threadIdx.x][j];
    }
}

// ------------------------------------------------------------------
// Launch 1: Encoder: gru_left (10 steps) -> gru_1 (1 step) -> heads + z
// ------------------------------------------------------------------
__global__ void __launch_bounds__(256) encoder_kernel(
    const float* __restrict__ X,
    const float* __restrict__ bih_l, const float* __restrict__ bhh_l,
    const float* __restrict__ bih1,  const float* __restrict__ bhh1,
    const float* __restrict__ bmu,   const float* __restrict__ bstd,
    const float* __restrict__ bmean, const float* __restrict__ bdisp,
    const float* __restrict__ z_noise,
    float* __restrict__ out_logvar, float* __restrict__ out_mu,
    float* __restrict__ out_mean,   float* __restrict__ out_disp)
{
    const int b = blockIdx.x;
    const int t = threadIdx.x;
    __shared__ float hs[HH];
    __shared__ float xs[PP];
    hs[t] = 0.0f;

    const float bir = bih_l[t]        + bhh_l[t];
    const float biz = bih_l[HH + t]   + bhh_l[HH + t];
    const float bin = bih_l[2*HH + t];
    const float bhn = bhh_l[2*HH + t];
    const float* __restrict__ Wh = g_WTenc + OFF_HHL;
    const float* __restrict__ Wi = g_WTenc + OFF_IHL;
    __syncthreads();

    for (int s = 0; s < 10; s++) {
        if (t < PP) xs[t] = X[((size_t)b * TT + s) * PP + t];
        __syncthreads();
        float ar = bir, az = biz, an = bin, gn = bhn;
        #pragma unroll 4
        for (int k = 0; k < HH; k++) {
            float hk = hs[k];
            ar += hk * Wh[k*768 + t];
            az += hk * Wh[k*768 + 256 + t];
            gn += hk * Wh[k*768 + 512 + t];
        }
        #pragma unroll 4
        for (int k = 0; k < PP; k++) {
            float xk = xs[k];
            ar += xk * Wi[k*768 + t];
            az += xk * Wi[k*768 + 256 + t];
            an += xk * Wi[k*768 + 512 + t];
        }
        float r  = fsig(ar);
        float zz = fsig(az);
        float n  = ftanh_(an + r * gn);
        float hnew = (1.0f - zz) * n + zz * hs[t];
        __syncthreads();
        hs[t] = hnew;
        __syncthreads();
    }

    {
        const float* __restrict__ W1 = g_WTenc + OFF_IH1;
        float ar = bih1[t]        + bhh1[t];
        float az = bih1[HH + t]   + bhh1[HH + t];
        float an = bih1[2*HH + t];
        float gn = bhh1[2*HH + t];
        #pragma unroll 4
        for (int k = 0; k < HH; k++) {
            float hk = hs[k];
            ar += hk * W1[k*768 + t];
            az += hk * W1[k*768 + 256 + t];
            an += hk * W1[k*768 + 512 + t];
        }
        float r  = fsig(ar);
        float zz = fsig(az);
        float n  = ftanh_(an + r * gn);
        float h1 = (1.0f - zz) * n;
        __syncthreads();
        hs[t] = h1;
        __syncthreads();
    }

    {
        float mu = bmu[t], lv = bstd[t];
        const float* __restrict__ Wm = g_WTenc + OFF_MU;
        const float* __restrict__ Ws = g_WTenc + OFF_STD;
        #pragma unroll 4
        for (int k = 0; k < HH; k++) {
            float hk = hs[k];
            mu += hk * Wm[k*256 + t];
            lv += hk * Ws[k*256 + t];
        }
        out_mu[b*HH + t]     = mu;
        out_logvar[b*HH + t] = lv;
        g_z[b*HH + t] = mu + expf(0.5f * lv) * z_noise[b*HH + t];

        if (t < PP) {
            float m = bmean[t], d = bdisp[t];
            const float* __restrict__ Wme = g_WTenc + OFF_MEAN;
            const float* __restrict__ Wd  = g_WTenc + OFF_DISP;
            #pragma unroll 4
            for (int k = 0; k < HH; k++) {
                float hk = hs[k];
                m += hk * Wme[k*64 + t];
                d += hk * Wd[k*64 + t];
            }
            m = expf(m);
            m = fminf(fmaxf(m, 1e-5f), 1e6f);
            d = log1pf(expf(d));
            d = fminf(fmaxf(d, 1e-4f), 1e4f);
            out_mean[b*PP + t] = m;
            out_disp[b*PP + t] = d;
        }
    }
}

// ------------------------------------------------------------------
// Launch 3: Per-series GRU nets — EXACT R13 kernel body (best: 4136us).
// Only change: 1-D grid + bid->(p,group) map exploiting classic
// placement smid = LUT[bid % 148]: bids b and b+148 share one SM, and
// the map gives them the SAME p -> identical weight streams -> the
// trailing CTA's weight preloads hit L1 instead of L2, and L2 weight
// traffic halves. Map covers all 256 (p,g) exactly once:
//   bid<108:      p = bid/2,        g = 2*(bid&1)        (g in {0,2})
//   108<=bid<148: s = bid-108: p = 54+s/4, g = s&3       (singles)
//   bid>=148:     j = bid-148: p = j/2,   g = 2*(j&1)+1  (g in {1,3})
// ------------------------------------------------------------------
#define BT 16
#define HST 20                 // hs row stride (16 batches + 4 pad)
#define WIH_F (KK * 768)       // 12288 floats = 48KB
#define NETS_SMEM_F (WIH_F + HH*HST + KK*HST + 128 + 16)

extern __shared__ float s_nets[];

__global__ void __launch_bounds__(256, 2) nets_kernel(
    const float* __restrict__ X,
    const int*   __restrict__ conn_idx,
    const float* __restrict__ bih,   // (P, 768)
    const float* __restrict__ bhh,   // (P, 768)
    const float* __restrict__ Wlin,  // (P, 1, 256)
    const float* __restrict__ blin,  // (P, 1)
    float* __restrict__ pred)        // (P, B, L, 1)
{
    // co-residency pairing map (see header comment)
    const int bid = blockIdx.x;
    int p, grp;
    if (bid < 108)       { p = bid >> 1;              grp = (bid & 1) << 1; }
    else if (bid < 148)  { int s = bid - 108;  p = 54 + (s >> 2); grp = s & 3; }
    else                 { int j = bid - 148;  p = j >> 1;  grp = ((j & 1) << 1) | 1; }
    const int b0c  = grp * BT;
    const int tid  = threadIdx.x;
    const int t    = tid;             // hidden unit
    const int lane = tid & 31;
    const int wg   = tid >> 5;        // warp 0..7

    float* wih_s = s_nets;                      // [16][768] staged input weights
    float* hs2   = s_nets + WIH_F;              // [k][16b] (stride 20)
    float* xg2   = hs2 + HH*HST;                // [k][16b]
    float* psum  = xg2 + KK*HST;                // [8][16]
    int*   cidx  = (int*)(psum + 128);          // [16]

    if (tid < KK) cidx[tid] = conn_idx[p*KK + tid];
    for (int i = tid; i < KK*HST; i += 256) xg2[i] = 0.0f;  // step 0 = zero row
    // stage input weights (step-invariant): 12288 floats, coalesced
    {
        const float* Wib = g_WTih + (size_t)p * WIH_F;
        for (int i = tid; i < WIH_F; i += 256) wih_s[i] = Wib[i];
    }
    #pragma unroll
    for (int j = 0; j < BT; j++)
        hs2[t*HST + j] = g_z[(size_t)(b0c + j) * HH + t];

    const size_t pb = (size_t)p * 768;
    const u64 brc2 = pk2(bih[pb + t]       + bhh[pb + t]);
    const u64 bzc2 = pk2(bih[pb + 256 + t] + bhh[pb + 256 + t]);
    const u64 bin2 = pk2(bih[pb + 512 + t]);
    const u64 bhn2 = pk2(bhh[pb + 512 + t]);
    const float wl  = Wlin[(size_t)p * HH + t];
    const float blv = blin[p];
    const float* __restrict__ Whp = g_WThh + (size_t)p * HH * 768 + t;  // [k][768]

    __syncthreads();

    for (int l = 0; l < LL; l++) {
        u64 ar2[8], az2[8], gi2[8], gh2[8];
        #pragma unroll
        for (int q = 0; q < 8; q++) { ar2[q]=brc2; az2[q]=bzc2; gi2[q]=bin2; gh2[q]=bhn2; }

        // input contribution (K = 16) — weights from SMEM (no LDG convoy)
        #pragma unroll
        for (int k = 0; k < KK; k++) {
            const float* r_ = wih_s + k * 768;
            const u64 wr = pk2(r_[t]);
            const u64 wz = pk2(r_[256 + t]);
            const u64 wn = pk2(r_[512 + t]);
            const ulonglong2* hp =
                reinterpret_cast<const ulonglong2*>(&xg2[k*HST]);
            #pragma unroll
            for (int q = 0; q < 4; q++) {
                ulonglong2 hv = hp[q];
                ar2[2*q]   = ffma2(hv.x, wr, ar2[2*q]);
                az2[2*q]   = ffma2(hv.x, wz, az2[2*q]);
                gi2[2*q]   = ffma2(hv.x, wn, gi2[2*q]);
                ar2[2*q+1] = ffma2(hv.y, wr, ar2[2*q+1]);
                az2[2*q+1] = ffma2(hv.y, wz, az2[2*q+1]);
                gi2[2*q+1] = ffma2(hv.y, wn, gi2[2*q+1]);
            }
        }

        // hidden contribution (H = 256) — chunks of 8 k:
        // phase 1 preloads 24 weight scalars; phase 2 is 192 FFMA2.
        #pragma unroll 1
        for (int kk = 0; kk < HH; kk += 8) {
            float wrf[8], wzf[8], wnf[8];
            #pragma unroll
            for (int j = 0; j < 8; j++) {
                const float* r_ = Whp + (size_t)(kk + j) * 768;
                wrf[j] = r_[0];
                wzf[j] = r_[256];
                wnf[j] = r_[512];
            }
            #pragma unroll
            for (int j = 0; j < 8; j++) {
                const u64 wr = pk2(wrf[j]);
                const u64 wz = pk2(wzf[j]);
                const u64 wn = pk2(wnf[j]);
                const ulonglong2* hp =
                    reinterpret_cast<const ulonglong2*>(&hs2[(kk + j)*HST]);
                #pragma unroll
                for (int q = 0; q < 4; q++) {
                    ulonglong2 hv = hp[q];
                    ar2[2*q]   = ffma2(hv.x, wr, ar2[2*q]);
                    az2[2*q]   = ffma2(hv.x, wz, az2[2*q]);
                    gh2[2*q]   = ffma2(hv.x, wn, gh2[2*q]);
                    ar2[2*q+1] = ffma2(hv.y, wr, ar2[2*q+1]);
                    az2[2*q+1] = ffma2(hv.y, wz, az2[2*q+1]);
                    gh2[2*q+1] = ffma2(hv.y, wn, gh2[2*q+1]);
                }
            }
        }

        // old h for the z-gate mix (read pre-barrier)
        float hold[16];
        #pragma unroll
        for (int j = 0; j < 4; j++) {
            float4 hv = *reinterpret_cast<const float4*>(&hs2[t*HST + 4*j]);
            hold[4*j]   = hv.x; hold[4*j+1] = hv.y;
            hold[4*j+2] = hv.z; hold[4*j+3] = hv.w;
        }

        float hnew[16];
        #pragma unroll
        for (int q = 0; q < 8; q++) {
            float a0,a1,z0,z1,i0,i1,n0,n1;
            upk2(ar2[q], a0, a1);
            upk2(az2[q], z0, z1);
            upk2(gi2[q], i0, i1);
            upk2(gh2[q], n0, n1);
            float r0 = fsig(a0), r1 = fsig(a1);
            float zz0 = fsig(z0), zz1 = fsig(z1);
            float nn0 = ftanh_(i0 + r0 * n0);
            float nn1 = ftanh_(i1 + r1 * n1);
            hnew[2*q]   = (1.0f - zz0) * nn0 + zz0 * hold[2*q];
            hnew[2*q+1] = (1.0f - zz1) * nn1 + zz1 * hold[2*q+1];
        }

        // pred partials from registers: warp-reduce per batch
        #pragma unroll
        for (int i = 0; i < 16; i++) {
            float v = fmaxf(hnew[i], 0.0f) * wl;
            v += __shfl_xor_sync(0xffffffffu, v, 16);
            v += __shfl_xor_sync(0xffffffffu, v, 8);
            v += __shfl_xor_sync(0xffffffffu, v, 4);
            v += __shfl_xor_sync(0xffffffffu, v, 2);
            v += __shfl_xor_sync(0xffffffffu, v, 1);
            if (lane == i) psum[wg*16 + i] = v;
        }

        __syncthreads();   // all reads of old hs2/xg2 + psum writes complete

        // commit new hidden state (k-major)
        #pragma unroll
        for (int j = 0; j < 4; j++) {
            *reinterpret_cast<float4*>(&hs2[t*HST + 4*j]) =
                make_float4(hnew[4*j], hnew[4*j+1], hnew[4*j+2], hnew[4*j+3]);
        }
        // gather inputs for step l+1: seq[l+1] = X[:, 10+l, conn]
        if (l < LL - 1) {
            int bb = tid >> 4, kk2 = tid & 15;   // 256 threads = 16 b x 16 k
            xg2[kk2*HST + bb] =
                X[((size_t)(b0c + bb) * TT + (10 + l)) * PP + cidx[kk2]];
        }
        // finalize pred for step l (psum visible post-barrier)
        if (tid < 16) {
            float s = 0.0f;
            #pragma unroll
            for (int w = 0; w < 8; w++) s += psum[w*16 + tid];
            pred[((size_t)(p*BB + b0c + tid)) * LL + l] = s + blv;
        }
        __syncthreads();   // hs2/xg2 writes + finalize visible before next compute
    }
}

extern "C" void kernel_launch(void* const* d_in, const int* in_sizes, int n_in,
                              void* d_out, int out_size)
{
    const float* X         = (const float*)d_in[0];
    const int*   conn_idx  = (const int*)  d_in[1];
    const float* W_ih_left = (const float*)d_in[2];
    const float* W_hh_left = (const float*)d_in[3];
    const float* b_ih_left = (const float*)d_in[4];
    const float* b_hh_left = (const float*)d_in[5];
    const float* W_ih_1    = (const float*)d_in[6];
    // d_in[7] = W_hh_1: unused (hidden state is 0 for gru_1's single step)
    const float* b_ih_1    = (const float*)d_in[8];
    const float* b_hh_1    = (const float*)d_in[9];
    const float* W_mu      = (const float*)d_in[10];
    const float* b_mu      = (const float*)d_in[11];
    const float* W_std     = (const float*)d_in[12];
    const float* b_std     = (const float*)d_in[13];
    const float* W_mean    = (const float*)d_in[14];
    const float* b_mean    = (const float*)d_in[15];
    const float* W_disp    = (const float*)d_in[16];
    const float* b_disp    = (const float*)d_in[17];
    const float* W_ih_nets = (const float*)d_in[18];
    const float* W_hh_nets = (const float*)d_in[19];
    const float* b_ih_nets = (const float*)d_in[20];
    const float* b_hh_nets = (const float*)d_in[21];
    const float* W_lin     = (const float*)d_in[22];
    const float* b_lin     = (const float*)d_in[23];
    const float* z_noise   = (const float*)d_in[24];

    float* out = (float*)d_out;
    float* pred       = out;
    float* out_logvar = out + 409600;
    float* out_mu     = out + 409600 + 16384;
    float* out_mean   = out + 409600 + 2*16384;
    float* out_disp   = out + 409600 + 2*16384 + 4096;

    float *wthh, *wtih, *wtenc;
    cudaGetSymbolAddress((void**)&wthh,  g_WThh);
    cudaGetSymbolAddress((void**)&wtih,  g_WTih);
    cudaGetSymbolAddress((void**)&wtenc, g_WTenc);

    const int nets_smem = NETS_SMEM_F * 4;
    cudaFuncSetAttribute(nets_kernel,
                         cudaFuncAttributeMaxDynamicSharedMemorySize, nets_smem);

    dim3 tb(32, 8);

    // Launch 0: all 7 encoder-weight transposes fused
    EncT7 e;
    e.in[0] = W_hh_left; e.out[0] = wtenc + OFF_HHL;  e.R[0] = 768; e.C[0] = 256;
    e.in[1] = W_ih_left; e.out[1] = wtenc + OFF_IHL;  e.R[1] = 768; e.C[1] = 64;
    e.in[2] = W_ih_1;    e.out[2] = wtenc + OFF_IH1;  e.R[2] = 768; e.C[2] = 256;
    e.in[3] = W_mu;      e.out[3] = wtenc + OFF_MU;   e.R[3] = 256; e.C[3] = 256;
    e.in[4] = W_std;     e.out[4] = wtenc + OFF_STD;  e.R[4] = 256; e.C[4] = 256;
    e.in[5] = W_mean;    e.out[5] = wtenc + OFF_MEAN; e.R[5] = 64;  e.C[5] = 256;
    e.in[6] = W_disp;    e.out[6] = wtenc + OFF_DISP; e.R[6] = 64;  e.C[6] = 256;
    transpose_multi7<<<dim3(8, 24, 7), tb>>>(e);

    // Launch 1: encoder (needs launch 0)
    encoder_kernel<<<BB, 256>>>(
        X, b_ih_left, b_hh_left, b_ih_1, b_hh_1,
        b_mu, b_std, b_mean, b_disp, z_noise,
        out_logvar, out_mu, out_mean, out_disp);

    // Launch 2: nets weight transposes fused (hh: z<64, ih: z>=64)
    transpose_nets<<<dim3(8, 24, 2*PP), tb>>>(W_hh_nets, W_ih_nets, wthh, wtih);

    // Launch 3: nets (profiled slot) — 1-D grid for the pairing map
    nets_kernel<<<256, 256, nets_smem>>>(
        X, conn_idx, b_ih_nets, b_hh_nets, W_lin, b_lin, pred);
}

// round 17
// speedup vs baseline: 1.1137x; 1.0337x over previous
#include <cuda_runtime.h>
#include <math.h>

// Problem dims
#define BB 64     // batch
#define TT 110    // timesteps
#define PP 64     // series
#define HH 256    // hidden
#define KK 16     // connections
#define LL 100    // nets seq length

typedef unsigned long long u64;

// Output layout (tuple concat, all f32):
//   pred   (P,B,L,1) : 409600  @ 0
//   logvar (B,H)     : 16384   @ 409600
//   mu     (B,H)     : 16384   @ 425984
//   mean   (B,P)     : 4096    @ 442368
//   disp   (B,P)     : 4096    @ 446464

__device__ float g_z[BB * HH];                       // latent z scratch
__device__ float g_WThh[(size_t)PP * HH * 768];      // 48MB: Whh_nets transposed [p][k][768]
__device__ float g_WTih[(size_t)PP * KK * 768];      // 3MB:  Wih_nets transposed [p][k][768]
__device__ float g_WTenc[606208];                    // encoder weights transposed

#define OFF_HHL  0        // W_hh_left^T  [256][768]
#define OFF_IHL  196608   // W_ih_left^T  [64][768]
#define OFF_IH1  245760   // W_ih_1^T     [256][768]
#define OFF_MU   442368   // W_mu^T       [256][256]
#define OFF_STD  507904   // W_std^T      [256][256]
#define OFF_MEAN 573440   // W_mean^T     [256][64]
#define OFF_DISP 589824   // W_disp^T     [256][64]

__device__ __forceinline__ u64 pk2(float x) {
    u64 r; asm("mov.b64 %0, {%1, %1};" : "=l"(r) : "f"(x)); return r;
}
__device__ __forceinline__ u64 ffma2(u64 a, u64 b, u64 c) {
    u64 d; asm("fma.rn.f32x2 %0, %1, %2, %3;" : "=l"(d) : "l"(a), "l"(b), "l"(c)); return d;
}
__device__ __forceinline__ void upk2(u64 a, float& lo, float& hi) {
    asm("mov.b64 {%0, %1}, %2;" : "=f"(lo), "=f"(hi) : "l"(a));
}
__device__ __forceinline__ float fsig(float x) {
    return __fdividef(1.0f, 1.0f + __expf(-x));
}
__device__ __forceinline__ float ftanh_(float x) {
    float e = __expf(fminf(fmaxf(2.0f * x, -80.0f), 80.0f));
    return __fdividef(e - 1.0f, e + 1.0f);
}

// ------------------------------------------------------------------
// Launch 0: fused transpose of all 7 encoder matrices (blockIdx.z = m)
// ------------------------------------------------------------------
struct EncT7 {
    const float* in[7];
    float*       out[7];
    int          R[7];
    int          C[7];
};
__global__ void transpose_multi7(EncT7 e)
{
    __shared__ float tile[32][33];
    const int m = blockIdx.z;
    const float* __restrict__ in = e.in[m];
    float* __restrict__ out = e.out[m];
    const int R = e.R[m], C = e.C[m];
    const int x = blockIdx.x * 32 + threadIdx.x;
    const int ybase = blockIdx.y * 32;
    #pragma unroll
    for (int j = threadIdx.y; j < 32; j += 8) {
        int y = ybase + j;
        if (x < C && y < R) tile[j][threadIdx.x] = in[(size_t)y * C + x];
    }
    __syncthreads();
    const int xo = ybase + threadIdx.x;
    const int yobase = blockIdx.x * 32;
    #pragma unroll
    for (int j = threadIdx.y; j < 32; j += 8) {
        int yo = yobase + j;
        if (yo < C && xo < R) out[(size_t)yo * R + xo] = tile[threadIdx.x][j];
    }
}

// ------------------------------------------------------------------
// Launch 2: fused transpose of nets weights.
// ------------------------------------------------------------------
__global__ void transpose_nets(const float* __restrict__ Whh,
                               const float* __restrict__ Wih,
                               float* __restrict__ outhh,
                               float* __restrict__ outih)
{
    __shared__ float tile[32][33];
    const int z = blockIdx.z;
    const float* __restrict__ in;
    float* __restrict__ out;
    int C;
    if (z < PP) {
        in  = Whh   + (size_t)z * 768 * HH;
        out = outhh + (size_t)z * HH * 768;
        C = HH;
    } else {
        in  = Wih   + (size_t)(z - PP) * 768 * KK;
        out = outih + (size_t)(z - PP) * KK * 768;
        C = KK;
    }
    const int R = 768;
    const int x = blockIdx.x * 32 + threadIdx.x;
    const int ybase = blockIdx.y * 32;
    #pragma unroll
    for (int j = threadIdx.y; j < 32; j += 8) {
        int y = ybase + j;
        if (x < C && y < R) tile[j][threadIdx.x] = in[(size_t)y * C + x];
    }
    __syncthreads();
    const int xo = ybase + threadIdx.x;
    const int yobase = blockIdx.x * 32;
    #pragma unroll
    for (int j = threadIdx.y; j < 32; j += 8) {
        int yo = yobase + j;
        if (yo < C && xo < R) out[(size_t)yo * R + xo] = tile[threadIdx.x][j];
    }
}

// ------------------------------------------------------------------
// Launch 1: Encoder: gru_left (10 steps) -> gru_1 (1 step) -> heads + z
// ------------------------------------------------------------------
__global__ void __launch_bounds__(256) encoder_kernel(
    const float* __restrict__ X,
    const float* __restrict__ bih_l, const float* __restrict__ bhh_l,
    const float* __restrict__ bih1,  const float* __restrict__ bhh1,
    const float* __restrict__ bmu,   const float* __restrict__ bstd,
    const float* __restrict__ bmean, const float* __restrict__ bdisp,
    const float* __restrict__ z_noise,
    float* __restrict__ out_logvar, float* __restrict__ out_mu,
    float* __restrict__ out_mean,   float* __restrict__ out_disp)
{
    const int b = blockIdx.x;
    const int t = threadIdx.x;
    __shared__ float hs[HH];
    __shared__ float xs[PP];
    hs[t] = 0.0f;

    const float bir = bih_l[t]        + bhh_l[t];
    const float biz = bih_l[HH + t]   + bhh_l[HH + t];
    const float bin = bih_l[2*HH + t];
    const float bhn = bhh_l[2*HH + t];
    const float* __restrict__ Wh = g_WTenc + OFF_HHL;
    const float* __restrict__ Wi = g_WTenc + OFF_IHL;
    __syncthreads();

    for (int s = 0; s < 10; s++) {
        if (t < PP) xs[t] = X[((size_t)b * TT + s) * PP + t];
        __syncthreads();
        float ar = bir, az = biz, an = bin, gn = bhn;
        #pragma unroll 4
        for (int k = 0; k < HH; k++) {
            float hk = hs[k];
            ar += hk * Wh[k*768 + t];
            az += hk * Wh[k*768 + 256 + t];
            gn += hk * Wh[k*768 + 512 + t];
        }
        #pragma unroll 4
        for (int k = 0; k < PP; k++) {
            float xk = xs[k];
            ar += xk * Wi[k*768 + t];
            az += xk * Wi[k*768 + 256 + t];
            an += xk * Wi[k*768 + 512 + t];
        }
        float r  = fsig(ar);
        float zz = fsig(az);
        float n  = ftanh_(an + r * gn);
        float hnew = (1.0f - zz) * n + zz * hs[t];
        __syncthreads();
        hs[t] = hnew;
        __syncthreads();
    }

    {
        const float* __restrict__ W1 = g_WTenc + OFF_IH1;
        float ar = bih1[t]        + bhh1[t];
        float az = bih1[HH + t]   + bhh1[HH + t];
        float an = bih1[2*HH + t];
        float gn = bhh1[2*HH + t];
        #pragma unroll 4
        for (int k = 0; k < HH; k++) {
            float hk = hs[k];
            ar += hk * W1[k*768 + t];
            az += hk * W1[k*768 + 256 + t];
            an += hk * W1[k*768 + 512 + t];
        }
        float r  = fsig(ar);
        float zz = fsig(az);
        float n  = ftanh_(an + r * gn);
        float h1 = (1.0f - zz) * n;
        __syncthreads();
        hs[t] = h1;
        __syncthreads();
    }

    {
        float mu = bmu[t], lv = bstd[t];
        const float* __restrict__ Wm = g_WTenc + OFF_MU;
        const float* __restrict__ Ws = g_WTenc + OFF_STD;
        #pragma unroll 4
        for (int k = 0; k < HH; k++) {
            float hk = hs[k];
            mu += hk * Wm[k*256 + t];
            lv += hk * Ws[k*256 + t];
        }
        out_mu[b*HH + t]     = mu;
        out_logvar[b*HH + t] = lv;
        g_z[b*HH + t] = mu + expf(0.5f * lv) * z_noise[b*HH + t];

        if (t < PP) {
            float m = bmean[t], d = bdisp[t];
            const float* __restrict__ Wme = g_WTenc + OFF_MEAN;
            const float* __restrict__ Wd  = g_WTenc + OFF_DISP;
            #pragma unroll 4
            for (int k = 0; k < HH; k++) {
                float hk = hs[k];
                m += hk * Wme[k*64 + t];
                d += hk * Wd[k*64 + t];
            }
            m = expf(m);
            m = fminf(fmaxf(m, 1e-5f), 1e6f);
            d = log1pf(expf(d));
            d = fminf(fmaxf(d, 1e-4f), 1e4f);
            out_mean[b*PP + t] = m;
            out_disp[b*PP + t] = d;
        }
    }
}

// ------------------------------------------------------------------
// Launch 3: Per-series GRU nets — R13 structure (best banked: 4136us)
// + WITHIN-STEP weight software pipeline (chunk=4, A/B reg buffers,
// static offsets, last iter peeled, NOTHING live across the barrier).
// Initial load hoisted above the SMEM-fed input phase (covers latency).
// grid (64,4), 256 thr, 2 CTAs/SM, dynamic SMEM ~72KB/CTA.
// ------------------------------------------------------------------
#define BT 16
#define HST 20                 // hs row stride (16 batches + 4 pad)
#define WIH_F (KK * 768)       // 12288 floats = 48KB
#define NETS_SMEM_F (WIH_F + HH*HST + KK*HST + 128 + 16)

extern __shared__ float s_nets[];

// load weights for 4 consecutive k into register buffer
#define HLOAD(KB, WR, WZ, WN)                                                 \
    _Pragma("unroll")                                                         \
    for (int j = 0; j < 4; j++) {                                             \
        const float* r_ = Whp + (size_t)((KB) + j) * 768;                     \
        WR[j] = r_[0];                                                        \
        WZ[j] = r_[256];                                                      \
        WN[j] = r_[512];                                                      \
    }

// FMA over 4 consecutive k from register buffer
#define HFMA(KB, WR, WZ, WN)                                                  \
    _Pragma("unroll")                                                         \
    for (int j = 0; j < 4; j++) {                                             \
        const u64 wr = pk2(WR[j]);                                            \
        const u64 wz = pk2(WZ[j]);                                            \
        const u64 wn = pk2(WN[j]);                                            \
        const ulonglong2* hp =                                                \
            reinterpret_cast<const ulonglong2*>(&hs2[((KB) + j)*HST]);        \
        _Pragma("unroll")                                                     \
        for (int q = 0; q < 4; q++) {                                         \
            ulonglong2 hv = hp[q];                                            \
            ar2[2*q]   = ffma2(hv.x, wr, ar2[2*q]);                           \
            az2[2*q]   = ffma2(hv.x, wz, az2[2*q]);                           \
            gh2[2*q]   = ffma2(hv.x, wn, gh2[2*q]);                           \
            ar2[2*q+1] = ffma2(hv.y, wr, ar2[2*q+1]);                         \
            az2[2*q+1] = ffma2(hv.y, wz, az2[2*q+1]);                         \
            gh2[2*q+1] = ffma2(hv.y, wn, gh2[2*q+1]);                         \
        }                                                                     \
    }

__global__ void __launch_bounds__(256, 2) nets_kernel(
    const float* __restrict__ X,
    const int*   __restrict__ conn_idx,
    const float* __restrict__ bih,   // (P, 768)
    const float* __restrict__ bhh,   // (P, 768)
    const float* __restrict__ Wlin,  // (P, 1, 256)
    const float* __restrict__ blin,  // (P, 1)
    float* __restrict__ pred)        // (P, B, L, 1)
{
    const int p    = blockIdx.x;
    const int b0c  = blockIdx.y * BT;
    const int tid  = threadIdx.x;
    const int t    = tid;             // hidden unit
    const int lane = tid & 31;
    const int wg   = tid >> 5;        // warp 0..7

    float* wih_s = s_nets;                      // [16][768] staged input weights
    float* hs2   = s_nets + WIH_F;              // [k][16b] (stride 20)
    float* xg2   = hs2 + HH*HST;                // [k][16b]
    float* psum  = xg2 + KK*HST;                // [8][16]
    int*   cidx  = (int*)(psum + 128);          // [16]

    if (tid < KK) cidx[tid] = conn_idx[p*KK + tid];
    for (int i = tid; i < KK*HST; i += 256) xg2[i] = 0.0f;  // step 0 = zero row
    // stage input weights (step-invariant): 12288 floats, coalesced
    {
        const float* Wib = g_WTih + (size_t)p * WIH_F;
        for (int i = tid; i < WIH_F; i += 256) wih_s[i] = Wib[i];
    }
    #pragma unroll
    for (int j = 0; j < BT; j++)
        hs2[t*HST + j] = g_z[(size_t)(b0c + j) * HH + t];

    const size_t pb = (size_t)p * 768;
    const u64 brc2 = pk2(bih[pb + t]       + bhh[pb + t]);
    const u64 bzc2 = pk2(bih[pb + 256 + t] + bhh[pb + 256 + t]);
    const u64 bin2 = pk2(bih[pb + 512 + t]);
    const u64 bhn2 = pk2(bhh[pb + 512 + t]);
    const float wl  = Wlin[(size_t)p * HH + t];
    const float blv = blin[p];
    const float* __restrict__ Whp = g_WThh + (size_t)p * HH * 768 + t;  // [k][768]

    __syncthreads();

    for (int l = 0; l < LL; l++) {
        u64 ar2[8], az2[8], gi2[8], gh2[8];
        #pragma unroll
        for (int q = 0; q < 8; q++) { ar2[q]=brc2; az2[q]=bzc2; gi2[q]=bin2; gh2[q]=bhn2; }

        // weight pipeline buffers (live only within this step's compute)
        float wrA[4], wzA[4], wnA[4];
        float wrB[4], wzB[4], wnB[4];
        HLOAD(0, wrA, wzA, wnA);   // latency covered by the input phase below

        // input contribution (K = 16) — weights from SMEM (no LDG convoy)
        #pragma unroll
        for (int k = 0; k < KK; k++) {
            const float* r_ = wih_s + k * 768;
            const u64 wr = pk2(r_[t]);
            const u64 wz = pk2(r_[256 + t]);
            const u64 wn = pk2(r_[512 + t]);
            const ulonglong2* hp =
                reinterpret_cast<const ulonglong2*>(&xg2[k*HST]);
            #pragma unroll
            for (int q = 0; q < 4; q++) {
                ulonglong2 hv = hp[q];
                ar2[2*q]   = ffma2(hv.x, wr, ar2[2*q]);
                az2[2*q]   = ffma2(hv.x, wz, az2[2*q]);
                gi2[2*q]   = ffma2(hv.x, wn, gi2[2*q]);
                ar2[2*q+1] = ffma2(hv.y, wr, ar2[2*q+1]);
                az2[2*q+1] = ffma2(hv.y, wz, az2[2*q+1]);
                gi2[2*q+1] = ffma2(hv.y, wn, gi2[2*q+1]);
            }
        }

        // hidden contribution (H = 256) — software-pipelined weight stream:
        // consume buffer while the other buffer's loads are in flight.
        #pragma unroll 1
        for (int kk = 0; kk < 248; kk += 8) {
            HLOAD(kk + 4, wrB, wzB, wnB);
            HFMA(kk, wrA, wzA, wnA);
            HLOAD(kk + 8, wrA, wzA, wnA);
            HFMA(kk + 4, wrB, wzB, wnB);
        }
        // peeled tail: kk = 248 (no further prefetch -> nothing live after)
        HLOAD(252, wrB, wzB, wnB);
        HFMA(248, wrA, wzA, wnA);
        HFMA(252, wrB, wzB, wnB);

        // old h for the z-gate mix (read pre-barrier)
        float hold[16];
        #pragma unroll
        for (int j = 0; j < 4; j++) {
            float4 hv = *reinterpret_cast<const float4*>(&hs2[t*HST + 4*j]);
            hold[4*j]   = hv.x; hold[4*j+1] = hv.y;
            hold[4*j+2] = hv.z; hold[4*j+3] = hv.w;
        }

        float hnew[16];
        #pragma unroll
        for (int q = 0; q < 8; q++) {
            float a0,a1,z0,z1,i0,i1,n0,n1;
            upk2(ar2[q], a0, a1);
            upk2(az2[q], z0, z1);
            upk2(gi2[q], i0, i1);
            upk2(gh2[q], n0, n1);
            float r0 = fsig(a0), r1 = fsig(a1);
            float zz0 = fsig(z0), zz1 = fsig(z1);
            float nn0 = ftanh_(i0 + r0 * n0);
            float nn1 = ftanh_(i1 + r1 * n1);
            hnew[2*q]   = (1.0f - zz0) * nn0 + zz0 * hold[2*q];
            hnew[2*q+1] = (1.0f - zz1) * nn1 + zz1 * hold[2*q+1];
        }

        // pred partials from registers: warp-reduce per batch
        #pragma unroll
        for (int i = 0; i < 16; i++) {
            float v = fmaxf(hnew[i], 0.0f) * wl;
            v += __shfl_xor_sync(0xffffffffu, v, 16);
            v += __shfl_xor_sync(0xffffffffu, v, 8);
            v += __shfl_xor_sync(0xffffffffu, v, 4);
            v += __shfl_xor_sync(0xffffffffu, v, 2);
            v += __shfl_xor_sync(0xffffffffu, v, 1);
            if (lane == i) psum[wg*16 + i] = v;
        }

        __syncthreads();   // all reads of old hs2/xg2 + psum writes complete

        // commit new hidden state (k-major)
        #pragma unroll
        for (int j = 0; j < 4; j++) {
            *reinterpret_cast<float4*>(&hs2[t*HST + 4*j]) =
                make_float4(hnew[4*j], hnew[4*j+1], hnew[4*j+2], hnew[4*j+3]);
        }
        // gather inputs for step l+1: seq[l+1] = X[:, 10+l, conn]
        if (l < LL - 1) {
            int bb = tid >> 4, kk2 = tid & 15;   // 256 threads = 16 b x 16 k
            xg2[kk2*HST + bb] =
                X[((size_t)(b0c + bb) * TT + (10 + l)) * PP + cidx[kk2]];
        }
        // finalize pred for step l (psum visible post-barrier)
        if (tid < 16) {
            float s = 0.0f;
            #pragma unroll
            for (int w = 0; w < 8; w++) s += psum[w*16 + tid];
            pred[((size_t)(p*BB + b0c + tid)) * LL + l] = s + blv;
        }
        __syncthreads();   // hs2/xg2 writes + finalize visible before next compute
    }
}

extern "C" void kernel_launch(void* const* d_in, const int* in_sizes, int n_in,
                              void* d_out, int out_size)
{
    const float* X         = (const float*)d_in[0];
    const int*   conn_idx  = (const int*)  d_in[1];
    const float* W_ih_left = (const float*)d_in[2];
    const float* W_hh_left = (const float*)d_in[3];
    const float* b_ih_left = (const float*)d_in[4];
    const float* b_hh_left = (const float*)d_in[5];
    const float* W_ih_1    = (const float*)d_in[6];
    // d_in[7] = W_hh_1: unused (hidden state is 0 for gru_1's single step)
    const float* b_ih_1    = (const float*)d_in[8];
    const float* b_hh_1    = (const float*)d_in[9];
    const float* W_mu      = (const float*)d_in[10];
    const float* b_mu      = (const float*)d_in[11];
    const float* W_std     = (const float*)d_in[12];
    const float* b_std     = (const float*)d_in[13];
    const float* W_mean    = (const float*)d_in[14];
    const float* b_mean    = (const float*)d_in[15];
    const float* W_disp    = (const float*)d_in[16];
    const float* b_disp    = (const float*)d_in[17];
    const float* W_ih_nets = (const float*)d_in[18];
    const float* W_hh_nets = (const float*)d_in[19];
    const float* b_ih_nets = (const float*)d_in[20];
    const float* b_hh_nets = (const float*)d_in[21];
    const float* W_lin     = (const float*)d_in[22];
    const float* b_lin     = (const float*)d_in[23];
    const float* z_noise   = (const float*)d_in[24];

    float* out = (float*)d_out;
    float* pred       = out;
    float* out_logvar = out + 409600;
    float* out_mu     = out + 409600 + 16384;
    float* out_mean   = out + 409600 + 2*16384;
    float* out_disp   = out + 409600 + 2*16384 + 4096;

    float *wthh, *wtih, *wtenc;
    cudaGetSymbolAddress((void**)&wthh,  g_WThh);
    cudaGetSymbolAddress((void**)&wtih,  g_WTih);
    cudaGetSymbolAddress((void**)&wtenc, g_WTenc);

    const int nets_smem = NETS_SMEM_F * 4;
    cudaFuncSetAttribute(nets_kernel,
                         cudaFuncAttributeMaxDynamicSharedMemorySize, nets_smem);

    dim3 tb(32, 8);

    // Launch 0: all 7 encoder-weight transposes fused
    EncT7 e;
    e.in[0] = W_hh_left; e.out[0] = wtenc + OFF_HHL;  e.R[0] = 768; e.C[0] = 256;
    e.in[1] = W_ih_left; e.out[1] = wtenc + OFF_IHL;  e.R[1] = 768; e.C[1] = 64;
    e.in[2] = W_ih_1;    e.out[2] = wtenc + OFF_IH1;  e.R[2] = 768; e.C[2] = 256;
    e.in[3] = W_mu;      e.out[3] = wtenc + OFF_MU;   e.R[3] = 256; e.C[3] = 256;
    e.in[4] = W_std;     e.out[4] = wtenc + OFF_STD;  e.R[4] = 256; e.C[4] = 256;
    e.in[5] = W_mean;    e.out[5] = wtenc + OFF_MEAN; e.R[5] = 64;  e.C[5] = 256;
    e.in[6] = W_disp;    e.out[6] = wtenc + OFF_DISP; e.R[6] = 64;  e.C[6] = 256;
    transpose_multi7<<<dim3(8, 24, 7), tb>>>(e);

    // Launch 1: encoder (needs launch 0)
    encoder_kernel<<<BB, 256>>>(
        X, b_ih_left, b_hh_left, b_ih_1, b_hh_1,
        b_mu, b_std, b_mean, b_disp, z_noise,
        out_logvar, out_mu, out_mean, out_disp);

    // Launch 2: nets weight transposes fused (hh: z<64, ih: z>=64)
    transpose_nets<<<dim3(8, 24, 2*PP), tb>>>(W_hh_nets, W_ih_nets, wthh, wtih);

    // Launch 3: nets (profiled slot)
    nets_kernel<<<dim3(PP, BB/BT), 256, nets_smem>>>(
        X, conn_idx, b_ih_nets, b_hh_nets, W_lin, b_lin, pred);
}